// round 6
// baseline (speedup 1.0000x reference)
#include <cuda_runtime.h>
#include <cstdint>
#include <cstddef>

// ---------------------------------------------------------------------------
// FullAttentionEstimator: B=2, Tq=Tk=512, Q_DIM=K_DIM=1024, HID=128
//
// Factorization:
//   q = Q@Wq, k = K@Wk                       (per-row, precomputed)
//   x = [q, k, q*k]  (384)
//   LN(x)@W = r*(x@(g.W)) - r*mu*(g@W) + (b@W + bias)
//   x@(g.W) = q@W1 + k@W2 + p@W3,  p = q*k  (per pair)
//   mu  = (Sq_i + Sk_j + sum(p))/384
//   E2  = (Sq2_i + Sk2_j + sum(p^2))/384, var = E2 - mu^2
// Cross term p@W3 (u|v stacked, N=256) is an fp32 GEMM done with packed
// fma.rn.f32x2 (FFMA2) in a persistent-CTA kernel; epilogue fuses gelu + Wo dot.
// ---------------------------------------------------------------------------

#define B_    2
#define TQ    512
#define TK    512
#define HID_  128
#define EPSV  1e-5f

// -------------------- device scratch (no allocations allowed) --------------
__device__ float dW1[128 * 256];     // g-scaled Wu|Wv rows 0..127   [c][n]
__device__ float dW2[128 * 256];     // rows 128..255
__device__ float dWc[128 * 256];     // rows 256..383 (cross weights)
__device__ float dG[256];            // sum_c g_c W[c][n]
__device__ float dB0[256];           // sum_c b_c W[c][n] + bias[n]
__device__ float d_q[1024 * 128];    // projected q rows (B*Tq)
__device__ float d_k[1024 * 128];
__device__ float dAu[1024 * 256];    // q@W1 (u|v)
__device__ float dBk[1024 * 256];    // k@W2 (u|v)
__device__ float dsq[1024], dsq2[1024], dsk[1024], dsk2[1024];

// -------------------- packed f32x2 helpers ---------------------------------
__device__ __forceinline__ unsigned long long pack2(float x) {
    unsigned long long r;
    asm("mov.b64 %0, {%1, %1};" : "=l"(r) : "r"(__float_as_uint(x)));
    return r;
}
__device__ __forceinline__ void unpack2(unsigned long long v, float& lo, float& hi) {
    asm("mov.b64 {%0, %1}, %2;" : "=f"(lo), "=f"(hi) : "l"(v));
}
#define FMA2(acc, a, b) \
    asm("fma.rn.f32x2 %0, %1, %2, %0;" : "+l"(acc) : "l"(a), "l"(b))

// ===========================================================================
// Kernel 1: derived weights (1 block, 256 threads; thread n = output column)
// ===========================================================================
__global__ void deriv_kernel(const float* __restrict__ ln_g, const float* __restrict__ ln_b,
                             const float* __restrict__ Wu,   const float* __restrict__ bu,
                             const float* __restrict__ Wv,   const float* __restrict__ bv) {
    const int n = threadIdx.x;  // 0..255 : n<128 -> u column n, else v column n-128
    float gacc = 0.f, bacc = 0.f;
    for (int c = 0; c < 384; c++) {
        float g = ln_g[c], bb = ln_b[c];
        float w = (n < 128) ? Wu[c * 128 + n] : Wv[c * 128 + (n - 128)];
        float gw = g * w;
        gacc += gw;
        bacc = fmaf(bb, w, bacc);
        float* dst = (c < 128) ? dW1 : ((c < 256) ? dW2 : dWc);
        dst[(c & 127) * 256 + n] = gw;
    }
    dG[n] = gacc;
    dB0[n] = bacc + ((n < 128) ? bu[n] : bv[n - 128]);
}

// ===========================================================================
// Kernel 2: projections. 128 blocks: 0..63 -> q rows, 64..127 -> k rows.
// Each block: 16 rows. Phase 1: row@Wq (K=1024). Phase 2: sums + row@W1/W2.
// ===========================================================================
__global__ __launch_bounds__(128, 1)
void proj_kernel(const float* __restrict__ Q, const float* __restrict__ K,
                 const float* __restrict__ Wq, const float* __restrict__ Wk) {
    extern __shared__ float sh[];  // 16*1024 floats = 64KB
    const int tid = threadIdx.x;
    const int half = blockIdx.x >> 6;           // 0=q, 1=k
    const int r0 = (blockIdx.x & 63) * 16;      // first global row
    const float* src = half ? K : Q;
    const float* W = half ? Wk : Wq;

    // stage 16 input rows (16 x 1024 fp32)
    {
        const float4* s4 = (const float4*)(src + (size_t)r0 * 1024);
        float4* d4 = (float4*)sh;
        for (int i = tid; i < 4096; i += 128) d4[i] = s4[i];
    }
    __syncthreads();

    float acc[16];
#pragma unroll
    for (int r = 0; r < 16; r++) acc[r] = 0.f;

    for (int d = 0; d < 1024; d += 4) {
        float w0 = W[(d + 0) * 128 + tid];
        float w1 = W[(d + 1) * 128 + tid];
        float w2 = W[(d + 2) * 128 + tid];
        float w3 = W[(d + 3) * 128 + tid];
#pragma unroll
        for (int r = 0; r < 16; r++) {
            float4 qv = *(const float4*)(sh + r * 1024 + d);
            acc[r] = fmaf(qv.x, w0, acc[r]);
            acc[r] = fmaf(qv.y, w1, acc[r]);
            acc[r] = fmaf(qv.z, w2, acc[r]);
            acc[r] = fmaf(qv.w, w3, acc[r]);
        }
    }
    __syncthreads();

    // write projected rows to smem (reuse) + global
    float* outq = half ? d_k : d_q;
#pragma unroll
    for (int r = 0; r < 16; r++) {
        sh[r * 128 + tid] = acc[r];
        outq[(size_t)(r0 + r) * 128 + tid] = acc[r];
    }
    __syncthreads();

    // per-row sums (16 threads, 1 row each)
    if (tid < 16) {
        float s = 0.f, s2 = 0.f;
        const float* row = sh + tid * 128;
        for (int c = 0; c < 128; c++) {
            float x = row[c];
            s += x;
            s2 = fmaf(x, x, s2);
        }
        if (half) { dsk[r0 + tid] = s; dsk2[r0 + tid] = s2; }
        else      { dsq[r0 + tid] = s; dsq2[r0 + tid] = s2; }
    }

    // A-projection: row @ W1 (or W2) -> (u|v)
    const float* Wp = half ? dW2 : dW1;
    float au[16], av[16];
#pragma unroll
    for (int r = 0; r < 16; r++) { au[r] = 0.f; av[r] = 0.f; }
    for (int c = 0; c < 128; c++) {
        float wu = Wp[c * 256 + tid];
        float wv = Wp[c * 256 + 128 + tid];
#pragma unroll
        for (int r = 0; r < 16; r++) {
            float qv = sh[r * 128 + c];
            au[r] = fmaf(qv, wu, au[r]);
            av[r] = fmaf(qv, wv, av[r]);
        }
    }
    float* outa = half ? dBk : dAu;
#pragma unroll
    for (int r = 0; r < 16; r++) {
        outa[(size_t)(r0 + r) * 256 + tid] = au[r];
        outa[(size_t)(r0 + r) * 256 + 128 + tid] = av[r];
    }
}

// ===========================================================================
// Kernel 3: main fused kernel. Persistent CTAs (1/SM), 256 threads each.
// Tile = 8 i x 8 j = 64 pairs; cross GEMM M=64, N=256, K=128 with FFMA2.
// smem layout in floats:
// ===========================================================================
#define OFF_WC   0        // 128*256 = 32768
#define OFF_PT   32768    // 128*72  = 9216  (p transposed, padded rows)
#define OFF_A    41984    // 8*256   = 2048
#define OFF_B    44032    // 8*256   = 2048
#define OFF_Q    46080    // 8*128   = 1024
#define OFF_K    47104    // 8*128   = 1024
#define OFF_G    48128    // 256
#define OFF_B0   48384    // 256
#define OFF_WO   48640    // 128
#define OFF_RED  48768    // 256
#define OFF_RED2 49024    // 256
#define OFF_R    49280    // 64
#define OFF_NR   49344    // 64
#define OFF_SC   49408    // 32 : sq[8] sq2[8] sk[8] sk2[8]
#define SMEM_FLOATS 49440
#define SMEM_MAIN (SMEM_FLOATS * 4)

#define NTILES (B_ * 64 * 64)   // 8192

#define GT(AU, BU, CU, GU, B0U, AV, BV, CV, GV, B0V, WO)                       \
    do {                                                                       \
        float u_ = fmaf(r, (AU) + (BU) + (CU), fmaf(nr, (GU), (B0U)));         \
        float v_ = fmaf(r, (AV) + (BV) + (CV), fmaf(nr, (GV), (B0V)));         \
        pd = fmaf(u_ * (v_ * normcdff(v_)), (WO), pd);                         \
    } while (0)

__global__ __launch_bounds__(256, 1)
void main_kernel(const float* __restrict__ Wo, const float* __restrict__ bo,
                 float* __restrict__ out) {
    extern __shared__ float sm[];
    const int tid = threadIdx.x;
    const int tx = tid & 31;   // N-group: 4 u-cols (tx*4..) + matching 4 v-cols
    const int ty = tid >> 5;   // M-group: i-row within tile, 8 pairs (j)

    // one-time loads: cross weights + G/B0/Wo
    {
        float4* wdst = (float4*)(sm + OFF_WC);
        const float4* wsrc = (const float4*)dWc;
        for (int i = tid; i < 8192; i += 256) wdst[i] = wsrc[i];
        sm[OFF_G + tid] = dG[tid];
        sm[OFF_B0 + tid] = dB0[tid];
        if (tid < 128) sm[OFF_WO + tid] = Wo[tid];
    }
    __syncthreads();

    const float4 Gu4 = *(const float4*)(sm + OFF_G + tx * 4);
    const float4 Gv4 = *(const float4*)(sm + OFF_G + 128 + tx * 4);
    const float4 B0u4 = *(const float4*)(sm + OFF_B0 + tx * 4);
    const float4 B0v4 = *(const float4*)(sm + OFF_B0 + 128 + tx * 4);
    const float4 Wo4 = *(const float4*)(sm + OFF_WO + tx * 4);
    const float bo_v = bo[0];

    for (int t = blockIdx.x; t < NTILES; t += gridDim.x) {
        const int b = t >> 12;
        const int i0 = ((t >> 6) & 63) * 8;
        const int j0 = (t & 63) * 8;

        __syncthreads();  // previous tile's epilogue done before smem reuse

        // ---- per-tile loads ----
        {
            const float4* qg = (const float4*)(d_q + (size_t)(b * 512 + i0) * 128);
            ((float4*)(sm + OFF_Q))[tid] = qg[tid];
            const float4* kg = (const float4*)(d_k + (size_t)(b * 512 + j0) * 128);
            ((float4*)(sm + OFF_K))[tid] = kg[tid];
            const float4* ag = (const float4*)(dAu + (size_t)(b * 512 + i0) * 256);
            ((float4*)(sm + OFF_A))[tid] = ag[tid];
            ((float4*)(sm + OFF_A))[256 + tid] = ag[256 + tid];
            const float4* bg = (const float4*)(dBk + (size_t)(b * 512 + j0) * 256);
            ((float4*)(sm + OFF_B))[tid] = bg[tid];
            ((float4*)(sm + OFF_B))[256 + tid] = bg[256 + tid];
            if (tid < 8)       sm[OFF_SC + tid] = dsq [b * 512 + i0 + tid];
            else if (tid < 16) sm[OFF_SC + tid] = dsq2[b * 512 + i0 + tid - 8];
            else if (tid < 24) sm[OFF_SC + tid] = dsk [b * 512 + j0 + tid - 16];
            else if (tid < 32) sm[OFF_SC + tid] = dsk2[b * 512 + j0 + tid - 24];
        }
        __syncthreads();

        // ---- build P^T [c][m] + partial row sums ----
        {
            const int m = tid & 63, ii = m >> 3, jj = m & 7, c0 = tid >> 6;
            const float* qrow = sm + OFF_Q + ii * 128;
            const float* krow = sm + OFF_K + jj * 128;
            float ls = 0.f, ls2 = 0.f;
#pragma unroll
            for (int s = 0; s < 32; s++) {
                int c = c0 + (s << 2);
                float p = qrow[c] * krow[c];
                sm[OFF_PT + c * 72 + m] = p;
                ls += p;
                ls2 = fmaf(p, p, ls2);
            }
            sm[OFF_RED + tid] = ls;
            sm[OFF_RED2 + tid] = ls2;
        }
        __syncthreads();

        // ---- per-pair LN statistics ----
        if (tid < 64) {
            float s = sm[OFF_RED + tid] + sm[OFF_RED + 64 + tid] +
                      sm[OFF_RED + 128 + tid] + sm[OFF_RED + 192 + tid];
            float s2 = sm[OFF_RED2 + tid] + sm[OFF_RED2 + 64 + tid] +
                       sm[OFF_RED2 + 128 + tid] + sm[OFF_RED2 + 192 + tid];
            int ii = tid >> 3, jj = tid & 7;
            float mu = (sm[OFF_SC + ii] + sm[OFF_SC + 16 + jj] + s) * (1.f / 384.f);
            float e2 = (sm[OFF_SC + 8 + ii] + sm[OFF_SC + 24 + jj] + s2) * (1.f / 384.f);
            float var = e2 - mu * mu;
            float r = rsqrtf(var + EPSV);
            sm[OFF_R + tid] = r;
            sm[OFF_NR + tid] = -r * mu;
        }
        __syncthreads();

        // ---- cross GEMM: C[64x256] = P[64x128] @ Wc[128x256] via FFMA2 ----
        unsigned long long aU[8][2], aV[8][2];
#pragma unroll
        for (int mi = 0; mi < 8; mi++) {
            aU[mi][0] = 0ull; aU[mi][1] = 0ull;
            aV[mi][0] = 0ull; aV[mi][1] = 0ull;
        }
        const float* ptBase = sm + OFF_PT + ty * 8;
        const unsigned long long* wBase =
            (const unsigned long long*)(sm + OFF_WC) + tx * 2;
#pragma unroll 2
        for (int k = 0; k < 128; k++) {
            const float4 x0 = *(const float4*)(ptBase + k * 72);
            const float4 x1 = *(const float4*)(ptBase + k * 72 + 4);
            const unsigned long long* wr = wBase + k * 128;
            unsigned long long wu0 = wr[0], wu1 = wr[1];
            unsigned long long wv0 = wr[64], wv1 = wr[65];
            float am[8] = {x0.x, x0.y, x0.z, x0.w, x1.x, x1.y, x1.z, x1.w};
#pragma unroll
            for (int mi = 0; mi < 8; mi++) {
                unsigned long long a2 = pack2(am[mi]);
                FMA2(aU[mi][0], a2, wu0);
                FMA2(aU[mi][1], a2, wu1);
                FMA2(aV[mi][0], a2, wv0);
                FMA2(aV[mi][1], a2, wv1);
            }
        }

        // ---- fused epilogue: LN recombine + gelu + Wo dot + warp reduce ----
        const float4 au = *(const float4*)(sm + OFF_A + ty * 256 + tx * 4);
        const float4 av = *(const float4*)(sm + OFF_A + ty * 256 + 128 + tx * 4);
#pragma unroll
        for (int mi = 0; mi < 8; mi++) {
            const int m = ty * 8 + mi;
            const float r = sm[OFF_R + m];
            const float nr = sm[OFF_NR + m];
            const float4 bu = *(const float4*)(sm + OFF_B + mi * 256 + tx * 4);
            const float4 bv = *(const float4*)(sm + OFF_B + mi * 256 + 128 + tx * 4);
            float cu0, cu1, cu2, cu3, cv0, cv1, cv2, cv3;
            unpack2(aU[mi][0], cu0, cu1);
            unpack2(aU[mi][1], cu2, cu3);
            unpack2(aV[mi][0], cv0, cv1);
            unpack2(aV[mi][1], cv2, cv3);
            float pd = 0.f;
            GT(au.x, bu.x, cu0, Gu4.x, B0u4.x, av.x, bv.x, cv0, Gv4.x, B0v4.x, Wo4.x);
            GT(au.y, bu.y, cu1, Gu4.y, B0u4.y, av.y, bv.y, cv1, Gv4.y, B0v4.y, Wo4.y);
            GT(au.z, bu.z, cu2, Gu4.z, B0u4.z, av.z, bv.z, cv2, Gv4.z, B0v4.z, Wo4.z);
            GT(au.w, bu.w, cu3, Gu4.w, B0u4.w, av.w, bv.w, cv3, Gv4.w, B0v4.w, Wo4.w);
#pragma unroll
            for (int o = 16; o > 0; o >>= 1)
                pd += __shfl_xor_sync(0xffffffffu, pd, o);
            if (tx == 0)
                out[((size_t)(b * 512 + i0 + ty)) * 512 + j0 + mi] = pd + bo_v;
        }
    }
}

// ===========================================================================
// launcher
// ===========================================================================
extern "C" void kernel_launch(void* const* d_in, const int* in_sizes, int n_in,
                              void* d_out, int out_size) {
    const float* Q    = (const float*)d_in[0];
    const float* K    = (const float*)d_in[1];
    const float* Wq   = (const float*)d_in[2];
    const float* Wk   = (const float*)d_in[3];
    const float* ln_g = (const float*)d_in[4];
    const float* ln_b = (const float*)d_in[5];
    const float* Wu   = (const float*)d_in[6];
    const float* bu   = (const float*)d_in[7];
    const float* Wv   = (const float*)d_in[8];
    const float* bv   = (const float*)d_in[9];
    const float* Wo   = (const float*)d_in[10];
    const float* bo   = (const float*)d_in[11];
    float* out = (float*)d_out;

    int nsm = 148;
    cudaDeviceGetAttribute(&nsm, cudaDevAttrMultiProcessorCount, 0);

    cudaFuncSetAttribute(proj_kernel, cudaFuncAttributeMaxDynamicSharedMemorySize, 65536);
    cudaFuncSetAttribute(main_kernel, cudaFuncAttributeMaxDynamicSharedMemorySize, SMEM_MAIN);

    deriv_kernel<<<1, 256>>>(ln_g, ln_b, Wu, bu, Wv, bv);
    proj_kernel<<<128, 128, 65536>>>(Q, K, Wq, Wk);
    main_kernel<<<nsm, 256, SMEM_MAIN>>>(Wo, bo, out);
}

// round 7
// speedup vs baseline: 1.0748x; 1.0748x over previous
#include <cuda_runtime.h>
#include <cstdint>
#include <cstddef>

// ---------------------------------------------------------------------------
// FullAttentionEstimator: B=2, Tq=Tk=512, Q_DIM=K_DIM=1024, HID=128
//
// Factorization:
//   q = Q@Wq, k = K@Wk                       (per-row, precomputed)
//   x = [q, k, q*k]  (384)
//   LN(x)@W = r*(x@(g.W)) - r*mu*(g@W) + (b@W + bias)
//   x@(g.W) = q@W1 + k@W2 + p@W3,  p = q*k  (per pair)
//   mu  = (Sq_i + Sk_j + sum(p))/384
//   E2  = (Sq2_i + Sk2_j + sum(p^2))/384, var = E2 - mu^2
// Cross term p@W3 (u|v stacked, N=256) is an fp32 GEMM with packed
// fma.rn.f32x2 (FFMA2) in a persistent-CTA kernel; per-tile operands are
// double-buffered (prefetch overlapped with the GEMM); epilogue fuses
// LN recombine (f32x2-packed) + exact gelu + Wo dot.
// ---------------------------------------------------------------------------

#define B_    2
#define HID_  128
#define EPSV  1e-5f

typedef unsigned long long ull;

// -------------------- device scratch (no allocations allowed) --------------
__device__ float dW1[128 * 256];     // g-scaled Wu|Wv rows 0..127   [c][n]
__device__ float dW2[128 * 256];     // rows 128..255
__device__ float dWc[128 * 256];     // rows 256..383 (cross weights)
__device__ float dG[256];            // sum_c g_c W[c][n]
__device__ float dB0[256];           // sum_c b_c W[c][n] + bias[n]
__device__ float d_q[1024 * 128];    // projected q rows (B*Tq)
__device__ float d_k[1024 * 128];
__device__ float dAu[1024 * 256];    // q@W1 (u|v)
__device__ float dBk[1024 * 256];    // k@W2 (u|v)
__device__ float dsq[1024], dsq2[1024], dsk[1024], dsk2[1024];

// -------------------- packed f32x2 helpers ---------------------------------
__device__ __forceinline__ ull pack2(float x) {
    ull r;
    asm("mov.b64 %0, {%1, %1};" : "=l"(r) : "r"(__float_as_uint(x)));
    return r;
}
__device__ __forceinline__ void unpack2(ull v, float& lo, float& hi) {
    asm("mov.b64 {%0, %1}, %2;" : "=f"(lo), "=f"(hi) : "l"(v));
}
__device__ __forceinline__ ull add2(ull a, ull b) {
    ull r;
    asm("add.rn.f32x2 %0, %1, %2;" : "=l"(r) : "l"(a), "l"(b));
    return r;
}
__device__ __forceinline__ ull fma2n(ull a, ull b, ull c) {
    ull r;
    asm("fma.rn.f32x2 %0, %1, %2, %3;" : "=l"(r) : "l"(a), "l"(b), "l"(c));
    return r;
}
#define FMA2(acc, a, b) \
    asm("fma.rn.f32x2 %0, %1, %2, %0;" : "+l"(acc) : "l"(a), "l"(b))

// ===========================================================================
// Kernel 1: derived weights. 256 blocks (one per output col n), 384 threads
// (one per LN channel c). Block-reduce for G / B0.
// ===========================================================================
__global__ void deriv_kernel(const float* __restrict__ ln_g, const float* __restrict__ ln_b,
                             const float* __restrict__ Wu,   const float* __restrict__ bu,
                             const float* __restrict__ Wv,   const float* __restrict__ bv) {
    __shared__ float sg[384], sb[384];
    const int n = blockIdx.x;     // 0..255
    const int c = threadIdx.x;    // 0..383
    float w = (n < 128) ? Wu[c * 128 + n] : Wv[c * 128 + (n - 128)];
    float gw = ln_g[c] * w;
    float bw = ln_b[c] * w;
    float* dst = (c < 128) ? dW1 : ((c < 256) ? dW2 : dWc);
    dst[(c & 127) * 256 + n] = gw;
    sg[c] = gw; sb[c] = bw;
    __syncthreads();
    if (c < 128) {
        sg[c] += sg[c + 128] + sg[c + 256];
        sb[c] += sb[c + 128] + sb[c + 256];
    }
    __syncthreads();
    if (c < 32) {
        float s = sg[c] + sg[c + 32] + sg[c + 64] + sg[c + 96];
        float t = sb[c] + sb[c + 32] + sb[c + 64] + sb[c + 96];
#pragma unroll
        for (int o = 16; o > 0; o >>= 1) {
            s += __shfl_xor_sync(0xffffffffu, s, o);
            t += __shfl_xor_sync(0xffffffffu, t, o);
        }
        if (c == 0) {
            dG[n] = s;
            dB0[n] = t + ((n < 128) ? bu[n] : bv[n - 128]);
        }
    }
}

// ===========================================================================
// Kernel 2: projections. 256 blocks: 0..127 -> q rows, 128..255 -> k rows.
// Each block: 8 rows, 128 threads (thread = output hidden col).
// ===========================================================================
__global__ __launch_bounds__(128, 2)
void proj_kernel(const float* __restrict__ Q, const float* __restrict__ K,
                 const float* __restrict__ Wq, const float* __restrict__ Wk) {
    __shared__ float sh[8 * 1024];  // 32KB
    const int tid = threadIdx.x;
    const int half = blockIdx.x >> 7;            // 0=q, 1=k
    const int r0 = (blockIdx.x & 127) * 8;       // first global row
    const float* src = half ? K : Q;
    const float* W = half ? Wk : Wq;

    {
        const float4* s4 = (const float4*)(src + (size_t)r0 * 1024);
        float4* d4 = (float4*)sh;
        for (int i = tid; i < 2048; i += 128) d4[i] = s4[i];
    }
    __syncthreads();

    float acc[8];
#pragma unroll
    for (int r = 0; r < 8; r++) acc[r] = 0.f;

    for (int d = 0; d < 1024; d += 4) {
        float w0 = W[(d + 0) * 128 + tid];
        float w1 = W[(d + 1) * 128 + tid];
        float w2 = W[(d + 2) * 128 + tid];
        float w3 = W[(d + 3) * 128 + tid];
#pragma unroll
        for (int r = 0; r < 8; r++) {
            float4 qv = *(const float4*)(sh + r * 1024 + d);
            acc[r] = fmaf(qv.x, w0, acc[r]);
            acc[r] = fmaf(qv.y, w1, acc[r]);
            acc[r] = fmaf(qv.z, w2, acc[r]);
            acc[r] = fmaf(qv.w, w3, acc[r]);
        }
    }
    __syncthreads();

    float* outq = half ? d_k : d_q;
#pragma unroll
    for (int r = 0; r < 8; r++) {
        sh[r * 128 + tid] = acc[r];
        outq[(size_t)(r0 + r) * 128 + tid] = acc[r];
    }
    __syncthreads();

    if (tid < 8) {
        float s = 0.f, s2 = 0.f;
        const float* row = sh + tid * 128;
        for (int c = 0; c < 128; c++) {
            float x = row[c];
            s += x;
            s2 = fmaf(x, x, s2);
        }
        if (half) { dsk[r0 + tid] = s; dsk2[r0 + tid] = s2; }
        else      { dsq[r0 + tid] = s; dsq2[r0 + tid] = s2; }
    }

    const float* Wp = half ? dW2 : dW1;
    float au[8], av[8];
#pragma unroll
    for (int r = 0; r < 8; r++) { au[r] = 0.f; av[r] = 0.f; }
    for (int c = 0; c < 128; c++) {
        float wu = Wp[c * 256 + tid];
        float wv = Wp[c * 256 + 128 + tid];
#pragma unroll
        for (int r = 0; r < 8; r++) {
            float qv = sh[r * 128 + c];
            au[r] = fmaf(qv, wu, au[r]);
            av[r] = fmaf(qv, wv, av[r]);
        }
    }
    float* outa = half ? dBk : dAu;
#pragma unroll
    for (int r = 0; r < 8; r++) {
        outa[(size_t)(r0 + r) * 256 + tid] = au[r];
        outa[(size_t)(r0 + r) * 256 + 128 + tid] = av[r];
    }
}

// ===========================================================================
// Kernel 3: main fused kernel. Persistent CTAs (1/SM), 256 threads.
// Tile = 8 i x 8 j = 64 pairs; cross GEMM M=64, N=256, K=128 via FFMA2.
// Per-tile operands double-buffered; prefetch overlapped with GEMM.
// ===========================================================================
#define OFF_WC   0        // 128*256 = 32768
#define OFF_PT   32768    // 128*72  = 9216  (p transposed, padded rows)
#define OFF_TB0  41984    // tile buffer 0 (6176 floats)
#define OFF_TB1  48160    // tile buffer 1
#define TB_SZ    6176
#define TB_A     0        // 8*256
#define TB_B     2048     // 8*256
#define TB_Q     4096     // 8*128
#define TB_K     5120     // 8*128
#define TB_SC    6144     // 32 : sq[8] sq2[8] sk[8] sk2[8]
#define OFF_G    54336    // 256
#define OFF_B0   54592    // 256
#define OFF_WO   54848    // 128
#define OFF_RED  54976    // 256
#define OFF_RED2 55232    // 256
#define OFF_R    55488    // 64
#define OFF_NR   55552    // 64
#define SMEM_FLOATS 55616
#define SMEM_MAIN (SMEM_FLOATS * 4)   // 222,464 B

#define NTILES (B_ * 64 * 64)   // 8192

__global__ __launch_bounds__(256, 1)
void main_kernel(const float* __restrict__ Wo, const float* __restrict__ bo,
                 float* __restrict__ out) {
    extern __shared__ float sm[];
    const int tid = threadIdx.x;
    const int tx = tid & 31;   // N-group: u cols tx*4..+3, v cols 128+tx*4..+3
    const int ty = tid >> 5;   // i-row within tile

    // one-time loads: cross weights + G/B0/Wo
    {
        float4* wdst = (float4*)(sm + OFF_WC);
        const float4* wsrc = (const float4*)dWc;
        for (int i = tid; i < 8192; i += 256) wdst[i] = wsrc[i];
        sm[OFF_G + tid] = dG[tid];
        sm[OFF_B0 + tid] = dB0[tid];
        if (tid < 128) sm[OFF_WO + tid] = Wo[tid];
    }
    __syncthreads();

    const ulonglong2 Gu2  = *(const ulonglong2*)(sm + OFF_G + tx * 4);
    const ulonglong2 Gv2  = *(const ulonglong2*)(sm + OFF_G + 128 + tx * 4);
    const ulonglong2 B0u2 = *(const ulonglong2*)(sm + OFF_B0 + tx * 4);
    const ulonglong2 B0v2 = *(const ulonglong2*)(sm + OFF_B0 + 128 + tx * 4);
    const float4 Wo4 = *(const float4*)(sm + OFF_WO + tx * 4);
    const float bo_v = bo[0];

    const int grid = gridDim.x;

    // ---- initial prefetch of tile t0 into buffer 0 ----
    {
        const int t = blockIdx.x;
        const int b = t >> 12, i0 = ((t >> 6) & 63) * 8, j0 = (t & 63) * 8;
        float* bufn = sm + OFF_TB0;
        ((float4*)(bufn + TB_Q))[tid] = ((const float4*)(d_q + (size_t)(b * 512 + i0) * 128))[tid];
        ((float4*)(bufn + TB_K))[tid] = ((const float4*)(d_k + (size_t)(b * 512 + j0) * 128))[tid];
        const float4* ag = (const float4*)(dAu + (size_t)(b * 512 + i0) * 256);
        ((float4*)(bufn + TB_A))[tid] = ag[tid];
        ((float4*)(bufn + TB_A))[256 + tid] = ag[256 + tid];
        const float4* bg = (const float4*)(dBk + (size_t)(b * 512 + j0) * 256);
        ((float4*)(bufn + TB_B))[tid] = bg[tid];
        ((float4*)(bufn + TB_B))[256 + tid] = bg[256 + tid];
        if (tid < 8)       bufn[TB_SC + tid] = dsq [b * 512 + i0 + tid];
        else if (tid < 16) bufn[TB_SC + tid] = dsq2[b * 512 + i0 + tid - 8];
        else if (tid < 24) bufn[TB_SC + tid] = dsk [b * 512 + j0 + tid - 16];
        else if (tid < 32) bufn[TB_SC + tid] = dsk2[b * 512 + j0 + tid - 24];
    }

    int cur = 0;
    for (int t = blockIdx.x; t < NTILES; t += grid) {
        const int b = t >> 12;
        const int i0 = ((t >> 6) & 63) * 8;
        const int j0 = (t & 63) * 8;
        float* bufc = sm + (cur ? OFF_TB1 : OFF_TB0);
        float* bufn = sm + (cur ? OFF_TB0 : OFF_TB1);

        // sync #1: prefetched buf[cur] visible; previous tile done with smem.
        __syncthreads();

        // ---- issue next-tile loads into registers (latency overlaps build) --
        const int tn = t + grid;
        const bool valid = tn < NTILES;
        float4 rq, rk, ra0, ra1, rb0, rb1;
        float rsc = 0.f;
        if (valid) {
            const int bn = tn >> 12, i0n = ((tn >> 6) & 63) * 8, j0n = (tn & 63) * 8;
            rq  = ((const float4*)(d_q + (size_t)(bn * 512 + i0n) * 128))[tid];
            rk  = ((const float4*)(d_k + (size_t)(bn * 512 + j0n) * 128))[tid];
            const float4* ag = (const float4*)(dAu + (size_t)(bn * 512 + i0n) * 256);
            ra0 = ag[tid]; ra1 = ag[256 + tid];
            const float4* bg = (const float4*)(dBk + (size_t)(bn * 512 + j0n) * 256);
            rb0 = bg[tid]; rb1 = bg[256 + tid];
            if (tid < 8)       rsc = dsq [bn * 512 + i0n + tid];
            else if (tid < 16) rsc = dsq2[bn * 512 + i0n + tid - 8];
            else if (tid < 24) rsc = dsk [bn * 512 + j0n + tid - 16];
            else if (tid < 32) rsc = dsk2[bn * 512 + j0n + tid - 24];
        }

        // ---- build P^T [c][m] + partial row sums ----
        {
            const int m = tid & 63, ii = m >> 3, jj = m & 7, c0 = tid >> 6;
            const float* qrow = bufc + TB_Q + ii * 128;
            const float* krow = bufc + TB_K + jj * 128;
            float ls = 0.f, ls2 = 0.f;
#pragma unroll
            for (int s = 0; s < 32; s++) {
                int c = c0 + (s << 2);
                float p = qrow[c] * krow[c];
                sm[OFF_PT + c * 72 + m] = p;
                ls += p;
                ls2 = fmaf(p, p, ls2);
            }
            sm[OFF_RED + tid] = ls;
            sm[OFF_RED2 + tid] = ls2;
        }

        // ---- commit prefetch to buf[nxt] ----
        if (valid) {
            ((float4*)(bufn + TB_Q))[tid] = rq;
            ((float4*)(bufn + TB_K))[tid] = rk;
            ((float4*)(bufn + TB_A))[tid] = ra0;
            ((float4*)(bufn + TB_A))[256 + tid] = ra1;
            ((float4*)(bufn + TB_B))[tid] = rb0;
            ((float4*)(bufn + TB_B))[256 + tid] = rb1;
            if (tid < 32) bufn[TB_SC + tid] = rsc;
        }

        // sync #2: P^T + partials (and prefetch STS) visible.
        __syncthreads();

        // ---- per-pair LN statistics ----
        if (tid < 64) {
            float s = sm[OFF_RED + tid] + sm[OFF_RED + 64 + tid] +
                      sm[OFF_RED + 128 + tid] + sm[OFF_RED + 192 + tid];
            float s2 = sm[OFF_RED2 + tid] + sm[OFF_RED2 + 64 + tid] +
                       sm[OFF_RED2 + 128 + tid] + sm[OFF_RED2 + 192 + tid];
            int ii = tid >> 3, jj = tid & 7;
            float mu = (bufc[TB_SC + ii] + bufc[TB_SC + 16 + jj] + s) * (1.f / 384.f);
            float e2 = (bufc[TB_SC + 8 + ii] + bufc[TB_SC + 24 + jj] + s2) * (1.f / 384.f);
            float var = e2 - mu * mu;
            float r = rsqrtf(var + EPSV);
            sm[OFF_R + tid] = r;
            sm[OFF_NR + tid] = -r * mu;
        }
        // sync #3: stats visible.
        __syncthreads();

        // ---- cross GEMM: C[64x256] = P[64x128] @ Wc[128x256] via FFMA2 ----
        ull aU[8][2], aV[8][2];
#pragma unroll
        for (int mi = 0; mi < 8; mi++) {
            aU[mi][0] = 0ull; aU[mi][1] = 0ull;
            aV[mi][0] = 0ull; aV[mi][1] = 0ull;
        }
        const float* ptBase = sm + OFF_PT + ty * 8;
        const float* wB = sm + OFF_WC + tx * 4;
#pragma unroll 2
        for (int k = 0; k < 128; k++) {
            const float4 x0 = *(const float4*)(ptBase + k * 72);
            const float4 x1 = *(const float4*)(ptBase + k * 72 + 4);
            const ulonglong2 wu = *(const ulonglong2*)(wB + k * 256);
            const ulonglong2 wv = *(const ulonglong2*)(wB + k * 256 + 128);
            float am[8] = {x0.x, x0.y, x0.z, x0.w, x1.x, x1.y, x1.z, x1.w};
#pragma unroll
            for (int mi = 0; mi < 8; mi++) {
                ull a2 = pack2(am[mi]);
                FMA2(aU[mi][0], a2, wu.x);
                FMA2(aU[mi][1], a2, wu.y);
                FMA2(aV[mi][0], a2, wv.x);
                FMA2(aV[mi][1], a2, wv.y);
            }
        }

        // ---- fused epilogue: packed LN recombine + gelu + Wo dot ----
        const ulonglong2 au2 = *(const ulonglong2*)(bufc + TB_A + ty * 256 + tx * 4);
        const ulonglong2 av2 = *(const ulonglong2*)(bufc + TB_A + ty * 256 + 128 + tx * 4);
#pragma unroll
        for (int mi = 0; mi < 8; mi++) {
            const int m = ty * 8 + mi;
            const ull r2  = pack2(sm[OFF_R + m]);
            const ull nr2 = pack2(sm[OFF_NR + m]);
            const ulonglong2 bu2 = *(const ulonglong2*)(bufc + TB_B + mi * 256 + tx * 4);
            const ulonglong2 bv2 = *(const ulonglong2*)(bufc + TB_B + mi * 256 + 128 + tx * 4);
            ull u0 = fma2n(r2, add2(add2(au2.x, bu2.x), aU[mi][0]),
                           fma2n(nr2, Gu2.x, B0u2.x));
            ull u1 = fma2n(r2, add2(add2(au2.y, bu2.y), aU[mi][1]),
                           fma2n(nr2, Gu2.y, B0u2.y));
            ull v0 = fma2n(r2, add2(add2(av2.x, bv2.x), aV[mi][0]),
                           fma2n(nr2, Gv2.x, B0v2.x));
            ull v1 = fma2n(r2, add2(add2(av2.y, bv2.y), aV[mi][1]),
                           fma2n(nr2, Gv2.y, B0v2.y));
            float ua, ub, uc, ud, va, vb, vc, vd;
            unpack2(u0, ua, ub); unpack2(u1, uc, ud);
            unpack2(v0, va, vb); unpack2(v1, vc, vd);
            float pd;
            pd = (ua * (va * normcdff(va))) * Wo4.x;
            pd = fmaf(ub * (vb * normcdff(vb)), Wo4.y, pd);
            pd = fmaf(uc * (vc * normcdff(vc)), Wo4.z, pd);
            pd = fmaf(ud * (vd * normcdff(vd)), Wo4.w, pd);
#pragma unroll
            for (int o = 16; o > 0; o >>= 1)
                pd += __shfl_xor_sync(0xffffffffu, pd, o);
            if (tx == 0)
                out[((size_t)(b * 512 + i0 + ty)) * 512 + j0 + mi] = pd + bo_v;
        }

        cur ^= 1;
    }
}

// ===========================================================================
// launcher
// ===========================================================================
extern "C" void kernel_launch(void* const* d_in, const int* in_sizes, int n_in,
                              void* d_out, int out_size) {
    const float* Q    = (const float*)d_in[0];
    const float* K    = (const float*)d_in[1];
    const float* Wq   = (const float*)d_in[2];
    const float* Wk   = (const float*)d_in[3];
    const float* ln_g = (const float*)d_in[4];
    const float* ln_b = (const float*)d_in[5];
    const float* Wu   = (const float*)d_in[6];
    const float* bu   = (const float*)d_in[7];
    const float* Wv   = (const float*)d_in[8];
    const float* bv   = (const float*)d_in[9];
    const float* Wo   = (const float*)d_in[10];
    const float* bo   = (const float*)d_in[11];
    float* out = (float*)d_out;

    int nsm = 148;
    cudaDeviceGetAttribute(&nsm, cudaDevAttrMultiProcessorCount, 0);

    cudaFuncSetAttribute(main_kernel, cudaFuncAttributeMaxDynamicSharedMemorySize, SMEM_MAIN);

    deriv_kernel<<<256, 384>>>(ln_g, ln_b, Wu, bu, Wv, bv);
    proj_kernel<<<256, 128>>>(Q, K, Wq, Wk);
    main_kernel<<<nsm, 256, SMEM_MAIN>>>(Wo, bo, out);
}

// round 8
// speedup vs baseline: 1.0763x; 1.0014x over previous
#include <cuda_runtime.h>
#include <cstdint>
#include <cstddef>

// ---------------------------------------------------------------------------
// FullAttentionEstimator: B=2, Tq=Tk=512, Q_DIM=K_DIM=1024, HID=128
//
// Factorization:
//   q = Q@Wq, k = K@Wk                       (per-row, precomputed)
//   x = [q, k, q*k]  (384)
//   LN(x)@W = r*(x@(g.W)) - r*mu*(g@W) + (b@W + bias)
//   x@(g.W) = q@W1 + k@W2 + p@W3,  p = q*k  (per pair)
//   mu  = (Sq_i + Sk_j + sum(p))/384
//   E2  = (Sq2_i + Sk2_j + sum(p^2))/384, var = E2 - mu^2
// Cross term p@W3 (u|v stacked, N=256) is an fp32 GEMM with packed
// fma.rn.f32x2 (FFMA2) in a persistent-CTA kernel; per-tile operands are
// double-buffered (prefetch overlapped with the GEMM); epilogue fuses
// LN recombine (f32x2-packed) + exact gelu + Wo dot.
// ---------------------------------------------------------------------------

#define B_    2
#define HID_  128
#define EPSV  1e-5f

typedef unsigned long long ull;

// -------------------- device scratch (no allocations allowed) --------------
__device__ float dW1[128 * 256];     // g-scaled Wu|Wv rows 0..127   [c][n]
__device__ float dW2[128 * 256];     // rows 128..255
__device__ float dWc[128 * 256];     // rows 256..383 (cross weights)
__device__ float dG[256];            // sum_c g_c W[c][n]
__device__ float dB0[256];           // sum_c b_c W[c][n] + bias[n]
__device__ float d_q[1024 * 128];    // projected q rows (B*Tq)
__device__ float d_k[1024 * 128];
__device__ float dAu[1024 * 256];    // q@W1 (u|v)
__device__ float dBk[1024 * 256];    // k@W2 (u|v)
__device__ float dsq[1024], dsq2[1024], dsk[1024], dsk2[1024];

// -------------------- packed f32x2 helpers ---------------------------------
__device__ __forceinline__ ull pack2(float x) {
    ull r;
    asm("mov.b64 %0, {%1, %1};" : "=l"(r) : "r"(__float_as_uint(x)));
    return r;
}
__device__ __forceinline__ void unpack2(ull v, float& lo, float& hi) {
    asm("mov.b64 {%0, %1}, %2;" : "=f"(lo), "=f"(hi) : "l"(v));
}
__device__ __forceinline__ ull add2(ull a, ull b) {
    ull r;
    asm("add.rn.f32x2 %0, %1, %2;" : "=l"(r) : "l"(a), "l"(b));
    return r;
}
__device__ __forceinline__ ull fma2n(ull a, ull b, ull c) {
    ull r;
    asm("fma.rn.f32x2 %0, %1, %2, %3;" : "=l"(r) : "l"(a), "l"(b), "l"(c));
    return r;
}
#define FMA2(acc, a, b) \
    asm("fma.rn.f32x2 %0, %1, %2, %0;" : "+l"(acc) : "l"(a), "l"(b))

// ===========================================================================
// Kernel 1: derived weights. 256 blocks (one per output col n), 384 threads
// (one per LN channel c). Block-reduce for G / B0.
// ===========================================================================
__global__ void deriv_kernel(const float* __restrict__ ln_g, const float* __restrict__ ln_b,
                             const float* __restrict__ Wu,   const float* __restrict__ bu,
                             const float* __restrict__ Wv,   const float* __restrict__ bv) {
    __shared__ float sg[384], sb[384];
    const int n = blockIdx.x;     // 0..255
    const int c = threadIdx.x;    // 0..383
    float w = (n < 128) ? Wu[c * 128 + n] : Wv[c * 128 + (n - 128)];
    float gw = ln_g[c] * w;
    float bw = ln_b[c] * w;
    float* dst = (c < 128) ? dW1 : ((c < 256) ? dW2 : dWc);
    dst[(c & 127) * 256 + n] = gw;
    sg[c] = gw; sb[c] = bw;
    __syncthreads();
    if (c < 128) {
        sg[c] += sg[c + 128] + sg[c + 256];
        sb[c] += sb[c + 128] + sb[c + 256];
    }
    __syncthreads();
    if (c < 32) {
        float s = sg[c] + sg[c + 32] + sg[c + 64] + sg[c + 96];
        float t = sb[c] + sb[c + 32] + sb[c + 64] + sb[c + 96];
#pragma unroll
        for (int o = 16; o > 0; o >>= 1) {
            s += __shfl_xor_sync(0xffffffffu, s, o);
            t += __shfl_xor_sync(0xffffffffu, t, o);
        }
        if (c == 0) {
            dG[n] = s;
            dB0[n] = t + ((n < 128) ? bu[n] : bv[n - 128]);
        }
    }
}

// ===========================================================================
// Kernel 2: projections. 256 blocks: 0..127 -> q rows, 128..255 -> k rows.
// Each block: 8 rows, 128 threads (thread = output hidden col).
// ===========================================================================
__global__ __launch_bounds__(128, 2)
void proj_kernel(const float* __restrict__ Q, const float* __restrict__ K,
                 const float* __restrict__ Wq, const float* __restrict__ Wk) {
    __shared__ float sh[8 * 1024];  // 32KB
    const int tid = threadIdx.x;
    const int half = blockIdx.x >> 7;            // 0=q, 1=k
    const int r0 = (blockIdx.x & 127) * 8;       // first global row
    const float* src = half ? K : Q;
    const float* W = half ? Wk : Wq;

    {
        const float4* s4 = (const float4*)(src + (size_t)r0 * 1024);
        float4* d4 = (float4*)sh;
        for (int i = tid; i < 2048; i += 128) d4[i] = s4[i];
    }
    __syncthreads();

    float acc[8];
#pragma unroll
    for (int r = 0; r < 8; r++) acc[r] = 0.f;

    for (int d = 0; d < 1024; d += 4) {
        float w0 = W[(d + 0) * 128 + tid];
        float w1 = W[(d + 1) * 128 + tid];
        float w2 = W[(d + 2) * 128 + tid];
        float w3 = W[(d + 3) * 128 + tid];
#pragma unroll
        for (int r = 0; r < 8; r++) {
            float4 qv = *(const float4*)(sh + r * 1024 + d);
            acc[r] = fmaf(qv.x, w0, acc[r]);
            acc[r] = fmaf(qv.y, w1, acc[r]);
            acc[r] = fmaf(qv.z, w2, acc[r]);
            acc[r] = fmaf(qv.w, w3, acc[r]);
        }
    }
    __syncthreads();

    float* outq = half ? d_k : d_q;
#pragma unroll
    for (int r = 0; r < 8; r++) {
        sh[r * 128 + tid] = acc[r];
        outq[(size_t)(r0 + r) * 128 + tid] = acc[r];
    }
    __syncthreads();

    if (tid < 8) {
        float s = 0.f, s2 = 0.f;
        const float* row = sh + tid * 128;
        for (int c = 0; c < 128; c++) {
            float x = row[c];
            s += x;
            s2 = fmaf(x, x, s2);
        }
        if (half) { dsk[r0 + tid] = s; dsk2[r0 + tid] = s2; }
        else      { dsq[r0 + tid] = s; dsq2[r0 + tid] = s2; }
    }

    const float* Wp = half ? dW2 : dW1;
    float au[8], av[8];
#pragma unroll
    for (int r = 0; r < 8; r++) { au[r] = 0.f; av[r] = 0.f; }
    for (int c = 0; c < 128; c++) {
        float wu = Wp[c * 256 + tid];
        float wv = Wp[c * 256 + 128 + tid];
#pragma unroll
        for (int r = 0; r < 8; r++) {
            float qv = sh[r * 128 + c];
            au[r] = fmaf(qv, wu, au[r]);
            av[r] = fmaf(qv, wv, av[r]);
        }
    }
    float* outa = half ? dBk : dAu;
#pragma unroll
    for (int r = 0; r < 8; r++) {
        outa[(size_t)(r0 + r) * 256 + tid] = au[r];
        outa[(size_t)(r0 + r) * 256 + 128 + tid] = av[r];
    }
}

// ===========================================================================
// Kernel 3: main fused kernel. Persistent CTAs (1/SM), 256 threads.
// Tile = 8 i x 8 j = 64 pairs; cross GEMM M=64, N=256, K=128 via FFMA2.
// Per-tile operands double-buffered; prefetch overlapped with GEMM.
// ===========================================================================
#define OFF_WC   0        // 128*256 = 32768
#define OFF_PT   32768    // 128*72  = 9216  (p transposed, padded rows)
#define OFF_TB0  41984    // tile buffer 0 (6176 floats)
#define OFF_TB1  48160    // tile buffer 1
#define TB_SZ    6176
#define TB_A     0        // 8*256
#define TB_B     2048     // 8*256
#define TB_Q     4096     // 8*128
#define TB_K     5120     // 8*128
#define TB_SC    6144     // 32 : sq[8] sq2[8] sk[8] sk2[8]
#define OFF_G    54336    // 256
#define OFF_B0   54592    // 256
#define OFF_WO   54848    // 128
#define OFF_RED  54976    // 256
#define OFF_RED2 55232    // 256
#define OFF_R    55488    // 64
#define OFF_NR   55552    // 64
#define SMEM_FLOATS 55616
#define SMEM_MAIN (SMEM_FLOATS * 4)   // 222,464 B

#define NTILES (B_ * 64 * 64)   // 8192

__global__ __launch_bounds__(256, 1)
void main_kernel(const float* __restrict__ Wo, const float* __restrict__ bo,
                 float* __restrict__ out) {
    extern __shared__ float sm[];
    const int tid = threadIdx.x;
    const int tx = tid & 31;   // N-group: u cols tx*4..+3, v cols 128+tx*4..+3
    const int ty = tid >> 5;   // i-row within tile

    // one-time loads: cross weights + G/B0/Wo
    {
        float4* wdst = (float4*)(sm + OFF_WC);
        const float4* wsrc = (const float4*)dWc;
        for (int i = tid; i < 8192; i += 256) wdst[i] = wsrc[i];
        sm[OFF_G + tid] = dG[tid];
        sm[OFF_B0 + tid] = dB0[tid];
        if (tid < 128) sm[OFF_WO + tid] = Wo[tid];
    }
    __syncthreads();

    const ulonglong2 Gu2  = *(const ulonglong2*)(sm + OFF_G + tx * 4);
    const ulonglong2 Gv2  = *(const ulonglong2*)(sm + OFF_G + 128 + tx * 4);
    const ulonglong2 B0u2 = *(const ulonglong2*)(sm + OFF_B0 + tx * 4);
    const ulonglong2 B0v2 = *(const ulonglong2*)(sm + OFF_B0 + 128 + tx * 4);
    const float4 Wo4 = *(const float4*)(sm + OFF_WO + tx * 4);
    const float bo_v = bo[0];

    const int grid = gridDim.x;

    // ---- initial prefetch of tile t0 into buffer 0 ----
    {
        const int t = blockIdx.x;
        const int b = t >> 12, i0 = ((t >> 6) & 63) * 8, j0 = (t & 63) * 8;
        float* bufn = sm + OFF_TB0;
        ((float4*)(bufn + TB_Q))[tid] = ((const float4*)(d_q + (size_t)(b * 512 + i0) * 128))[tid];
        ((float4*)(bufn + TB_K))[tid] = ((const float4*)(d_k + (size_t)(b * 512 + j0) * 128))[tid];
        const float4* ag = (const float4*)(dAu + (size_t)(b * 512 + i0) * 256);
        ((float4*)(bufn + TB_A))[tid] = ag[tid];
        ((float4*)(bufn + TB_A))[256 + tid] = ag[256 + tid];
        const float4* bg = (const float4*)(dBk + (size_t)(b * 512 + j0) * 256);
        ((float4*)(bufn + TB_B))[tid] = bg[tid];
        ((float4*)(bufn + TB_B))[256 + tid] = bg[256 + tid];
        if (tid < 8)       bufn[TB_SC + tid] = dsq [b * 512 + i0 + tid];
        else if (tid < 16) bufn[TB_SC + tid] = dsq2[b * 512 + i0 + tid - 8];
        else if (tid < 24) bufn[TB_SC + tid] = dsk [b * 512 + j0 + tid - 16];
        else if (tid < 32) bufn[TB_SC + tid] = dsk2[b * 512 + j0 + tid - 24];
    }

    int cur = 0;
    for (int t = blockIdx.x; t < NTILES; t += grid) {
        const int b = t >> 12;
        const int i0 = ((t >> 6) & 63) * 8;
        const int j0 = (t & 63) * 8;
        float* bufc = sm + (cur ? OFF_TB1 : OFF_TB0);
        float* bufn = sm + (cur ? OFF_TB0 : OFF_TB1);

        // sync #1: prefetched buf[cur] visible; previous tile done with smem.
        __syncthreads();

        // ---- issue next-tile loads into registers (latency overlaps build) --
        const int tn = t + grid;
        const bool valid = tn < NTILES;
        float4 rq, rk, ra0, ra1, rb0, rb1;
        float rsc = 0.f;
        if (valid) {
            const int bn = tn >> 12, i0n = ((tn >> 6) & 63) * 8, j0n = (tn & 63) * 8;
            rq  = ((const float4*)(d_q + (size_t)(bn * 512 + i0n) * 128))[tid];
            rk  = ((const float4*)(d_k + (size_t)(bn * 512 + j0n) * 128))[tid];
            const float4* ag = (const float4*)(dAu + (size_t)(bn * 512 + i0n) * 256);
            ra0 = ag[tid]; ra1 = ag[256 + tid];
            const float4* bg = (const float4*)(dBk + (size_t)(bn * 512 + j0n) * 256);
            rb0 = bg[tid]; rb1 = bg[256 + tid];
            if (tid < 8)       rsc = dsq [bn * 512 + i0n + tid];
            else if (tid < 16) rsc = dsq2[bn * 512 + i0n + tid - 8];
            else if (tid < 24) rsc = dsk [bn * 512 + j0n + tid - 16];
            else if (tid < 32) rsc = dsk2[bn * 512 + j0n + tid - 24];
        }

        // ---- build P^T [c][m] + partial row sums ----
        {
            const int m = tid & 63, ii = m >> 3, jj = m & 7, c0 = tid >> 6;
            const float* qrow = bufc + TB_Q + ii * 128;
            const float* krow = bufc + TB_K + jj * 128;
            float ls = 0.f, ls2 = 0.f;
#pragma unroll
            for (int s = 0; s < 32; s++) {
                int c = c0 + (s << 2);
                float p = qrow[c] * krow[c];
                sm[OFF_PT + c * 72 + m] = p;
                ls += p;
                ls2 = fmaf(p, p, ls2);
            }
            sm[OFF_RED + tid] = ls;
            sm[OFF_RED2 + tid] = ls2;
        }

        // ---- commit prefetch to buf[nxt] ----
        if (valid) {
            ((float4*)(bufn + TB_Q))[tid] = rq;
            ((float4*)(bufn + TB_K))[tid] = rk;
            ((float4*)(bufn + TB_A))[tid] = ra0;
            ((float4*)(bufn + TB_A))[256 + tid] = ra1;
            ((float4*)(bufn + TB_B))[tid] = rb0;
            ((float4*)(bufn + TB_B))[256 + tid] = rb1;
            if (tid < 32) bufn[TB_SC + tid] = rsc;
        }

        // sync #2: P^T + partials (and prefetch STS) visible.
        __syncthreads();

        // ---- per-pair LN statistics ----
        if (tid < 64) {
            float s = sm[OFF_RED + tid] + sm[OFF_RED + 64 + tid] +
                      sm[OFF_RED + 128 + tid] + sm[OFF_RED + 192 + tid];
            float s2 = sm[OFF_RED2 + tid] + sm[OFF_RED2 + 64 + tid] +
                       sm[OFF_RED2 + 128 + tid] + sm[OFF_RED2 + 192 + tid];
            int ii = tid >> 3, jj = tid & 7;
            float mu = (bufc[TB_SC + ii] + bufc[TB_SC + 16 + jj] + s) * (1.f / 384.f);
            float e2 = (bufc[TB_SC + 8 + ii] + bufc[TB_SC + 24 + jj] + s2) * (1.f / 384.f);
            float var = e2 - mu * mu;
            float r = rsqrtf(var + EPSV);
            sm[OFF_R + tid] = r;
            sm[OFF_NR + tid] = -r * mu;
        }
        // sync #3: stats visible.
        __syncthreads();

        // ---- cross GEMM: C[64x256] = P[64x128] @ Wc[128x256] via FFMA2 ----
        ull aU[8][2], aV[8][2];
#pragma unroll
        for (int mi = 0; mi < 8; mi++) {
            aU[mi][0] = 0ull; aU[mi][1] = 0ull;
            aV[mi][0] = 0ull; aV[mi][1] = 0ull;
        }
        const float* ptBase = sm + OFF_PT + ty * 8;
        const float* wB = sm + OFF_WC + tx * 4;
#pragma unroll 2
        for (int k = 0; k < 128; k++) {
            const float4 x0 = *(const float4*)(ptBase + k * 72);
            const float4 x1 = *(const float4*)(ptBase + k * 72 + 4);
            const ulonglong2 wu = *(const ulonglong2*)(wB + k * 256);
            const ulonglong2 wv = *(const ulonglong2*)(wB + k * 256 + 128);
            float am[8] = {x0.x, x0.y, x0.z, x0.w, x1.x, x1.y, x1.z, x1.w};
#pragma unroll
            for (int mi = 0; mi < 8; mi++) {
                ull a2 = pack2(am[mi]);
                FMA2(aU[mi][0], a2, wu.x);
                FMA2(aU[mi][1], a2, wu.y);
                FMA2(aV[mi][0], a2, wv.x);
                FMA2(aV[mi][1], a2, wv.y);
            }
        }

        // ---- fused epilogue: packed LN recombine + gelu + Wo dot ----
        const ulonglong2 au2 = *(const ulonglong2*)(bufc + TB_A + ty * 256 + tx * 4);
        const ulonglong2 av2 = *(const ulonglong2*)(bufc + TB_A + ty * 256 + 128 + tx * 4);
#pragma unroll
        for (int mi = 0; mi < 8; mi++) {
            const int m = ty * 8 + mi;
            const ull r2  = pack2(sm[OFF_R + m]);
            const ull nr2 = pack2(sm[OFF_NR + m]);
            const ulonglong2 bu2 = *(const ulonglong2*)(bufc + TB_B + mi * 256 + tx * 4);
            const ulonglong2 bv2 = *(const ulonglong2*)(bufc + TB_B + mi * 256 + 128 + tx * 4);
            ull u0 = fma2n(r2, add2(add2(au2.x, bu2.x), aU[mi][0]),
                           fma2n(nr2, Gu2.x, B0u2.x));
            ull u1 = fma2n(r2, add2(add2(au2.y, bu2.y), aU[mi][1]),
                           fma2n(nr2, Gu2.y, B0u2.y));
            ull v0 = fma2n(r2, add2(add2(av2.x, bv2.x), aV[mi][0]),
                           fma2n(nr2, Gv2.x, B0v2.x));
            ull v1 = fma2n(r2, add2(add2(av2.y, bv2.y), aV[mi][1]),
                           fma2n(nr2, Gv2.y, B0v2.y));
            float ua, ub, uc, ud, va, vb, vc, vd;
            unpack2(u0, ua, ub); unpack2(u1, uc, ud);
            unpack2(v0, va, vb); unpack2(v1, vc, vd);
            float pd;
            pd = (ua * (va * normcdff(va))) * Wo4.x;
            pd = fmaf(ub * (vb * normcdff(vb)), Wo4.y, pd);
            pd = fmaf(uc * (vc * normcdff(vc)), Wo4.z, pd);
            pd = fmaf(ud * (vd * normcdff(vd)), Wo4.w, pd);
#pragma unroll
            for (int o = 16; o > 0; o >>= 1)
                pd += __shfl_xor_sync(0xffffffffu, pd, o);
            if (tx == 0)
                out[((size_t)(b * 512 + i0 + ty)) * 512 + j0 + mi] = pd + bo_v;
        }

        cur ^= 1;
    }
}

// ===========================================================================
// launcher
// ===========================================================================
extern "C" void kernel_launch(void* const* d_in, const int* in_sizes, int n_in,
                              void* d_out, int out_size) {
    const float* Q    = (const float*)d_in[0];
    const float* K    = (const float*)d_in[1];
    const float* Wq   = (const float*)d_in[2];
    const float* Wk   = (const float*)d_in[3];
    const float* ln_g = (const float*)d_in[4];
    const float* ln_b = (const float*)d_in[5];
    const float* Wu   = (const float*)d_in[6];
    const float* bu   = (const float*)d_in[7];
    const float* Wv   = (const float*)d_in[8];
    const float* bv   = (const float*)d_in[9];
    const float* Wo   = (const float*)d_in[10];
    const float* bo   = (const float*)d_in[11];
    float* out = (float*)d_out;

    int nsm = 148;
    cudaDeviceGetAttribute(&nsm, cudaDevAttrMultiProcessorCount, 0);

    cudaFuncSetAttribute(main_kernel, cudaFuncAttributeMaxDynamicSharedMemorySize, SMEM_MAIN);

    deriv_kernel<<<256, 384>>>(ln_g, ln_b, Wu, bu, Wv, bv);
    proj_kernel<<<256, 128>>>(Q, K, Wq, Wk);
    main_kernel<<<nsm, 256, SMEM_MAIN>>>(Wo, bo, out);
}